// round 11
// baseline (speedup 1.0000x reference)
#include <cuda_runtime.h>
#include <cuda_fp16.h>
#include <math.h>
#include <cstdint>

#define BATCH 4096
#define UNITS 1024
#define OUT_STEPS 200
#define SEQ_LEN 5

#define BK 64
#define NSTG 16          // merged stages: each does k64 against B_hi AND B_lo
#define BM 128
#define BN 128           // permuted z columns (= 32 units x 4 gates)
#define NTHREADS 256

#define A_STG 16384                     // 128 rows x 128B (k64 fp16)
#define STG_BYTES (3 * 16384)           // A + B_hi + B_lo = 48KB
#define NBUF 2
#define SMEM_TOTAL (NBUF * STG_BYTES)   // 96KB -> 2 CTAs/SM

// ---------------- device globals ----------------
__device__ __half g_A[2][BATCH * 1024];   // ping-pong hidden state, fp16
__device__ __half g_B[4096 * 2048];       // permuted split R: row C, [R_hi(1024) | R_lo(1024)]
__device__ float g_c[BATCH * UNITS];
__device__ float g_pred[BATCH];
__device__ float g_kwP[4096];
__device__ float g_biasP[4096];

// ---------------- helpers ----------------
__device__ __forceinline__ uint32_t smem_u32(const void* p) {
    uint32_t a;
    asm("{ .reg .u64 t; cvta.to.shared.u64 t, %1; cvt.u32.u64 %0, t; }" : "=r"(a) : "l"(p));
    return a;
}
__device__ __forceinline__ void cp16(uint32_t saddr, const void* gaddr) {
    asm volatile("cp.async.cg.shared.global [%0], [%1], 16;" :: "r"(saddr), "l"(gaddr));
}
__device__ __forceinline__ void cp_commit() {
    asm volatile("cp.async.commit_group;" ::: "memory");
}
template<int N> __device__ __forceinline__ void cp_wait() {
    asm volatile("cp.async.wait_group %0;" :: "n"(N) : "memory");
}
__device__ __forceinline__ void ldsm4(uint32_t* r, uint32_t addr) {
    asm volatile("ldmatrix.sync.aligned.m8n8.x4.shared.b16 {%0,%1,%2,%3}, [%4];"
                 : "=r"(r[0]), "=r"(r[1]), "=r"(r[2]), "=r"(r[3]) : "r"(addr));
}
__device__ __forceinline__ void mma16816(float* c, const uint32_t* a, const uint32_t* b) {
    asm volatile(
        "mma.sync.aligned.m16n8k16.row.col.f32.f16.f16.f32 "
        "{%0,%1,%2,%3}, {%4,%5,%6,%7}, {%8,%9}, {%0,%1,%2,%3};"
        : "+f"(c[0]), "+f"(c[1]), "+f"(c[2]), "+f"(c[3])
        : "r"(a[0]), "r"(a[1]), "r"(a[2]), "r"(a[3]), "r"(b[0]), "r"(b[1]));
}
__device__ __forceinline__ float sigm(float x) { return 1.0f / (1.0f + __expf(-x)); }
__device__ __forceinline__ float tanh_fast(float x) {
    float t = __expf(-2.0f * fabsf(x));
    float r = (1.0f - t) / (1.0f + t);
    return copysignf(r, x);
}

// ---------------- prep: build permuted split-fp16 B ----------------
// NEW permutation (gate-pair bit moved to bit3 so a 32-col warp owns all 4 gates):
//   C = (u>>3)*32 + ((u>>2)&1)*16 + (g>>1)*8 + (u&3)*2 + (g&1)
// Inverse: g = (np&1) | (((np>>3)&1)<<1)
//          u = ((np>>5)<<3) | (((np>>4)&1)<<2) | ((np>>1)&3)
__global__ void prep_kernel(const float* __restrict__ R, const float* __restrict__ Kw,
                            const float* __restrict__ bias) {
    int idx = blockIdx.x * blockDim.x + threadIdx.x;   // np*1024 + k
    if (idx >= 4096 * 1024) return;
    int np = idx >> 10;
    int k  = idx & 1023;
    int g = (np & 1) | (((np >> 3) & 1) << 1);
    int u = ((np >> 5) << 3) | (((np >> 4) & 1) << 2) | ((np >> 1) & 3);
    int n = g * 1024 + u;
    float v = R[k * 4096 + n];
    __half hi = __float2half_rn(v);
    __half lo = __float2half_rn(v - __half2float(hi));
    g_B[np * 2048 + k]        = hi;
    g_B[np * 2048 + 1024 + k] = lo;
    if (k == 0) { g_kwP[np] = Kw[n]; g_biasP[np] = bias[n]; }
}

__global__ void zero_kernel() {
    int i = blockIdx.x * blockDim.x + threadIdx.x;
    if (i < BATCH * UNITS) {
        g_c[i] = 0.0f;
        if (i < BATCH * 512) ((uint32_t*)g_A[0])[i] = 0;   // 2M halfs
    }
}

// ---------------- fused LSTM step (fp16 mma.sync dual-B GEMM + gates) ----------------
__global__ void __launch_bounds__(NTHREADS, 2) lstm_mma(const float* __restrict__ xsrc,
                                                        int xstride, int pin) {
    extern __shared__ char smem[];
    const uint32_t sb = smem_u32(smem);
    const int tid  = threadIdx.x;
    const int wid  = tid >> 5;
    const int lane = tid & 31;
    const int wm   = wid >> 2;       // 0..1 (64-row group)
    const int wn   = wid & 3;        // 0..3 (32-col group)
    const int krot = wid & 3;        // kk-phase rotation per warp
    const int m0   = blockIdx.x * BM;
    const int n0p  = blockIdx.y * BN;   // permuted-col base

    const __half* __restrict__ Ain = g_A[pin];
    __half* __restrict__ Aout = g_A[pin ^ 1];

    float acc[4][4][4];   // [mi (16-row tile)][j (n8 tile)][frag]
    #pragma unroll
    for (int a = 0; a < 4; a++)
        #pragma unroll
        for (int b = 0; b < 4; b++)
            #pragma unroll
            for (int c = 0; c < 4; c++) acc[a][b][c] = 0.0f;

    const int cprow = tid >> 3;     // 0..31
    const int cpch  = tid & 7;

    auto issue = [&](int s) {
        const int buf = s & (NBUF - 1);
        const int kk0 = s * BK;
        const uint32_t ab = sb + buf * STG_BYTES;
        const uint32_t bh = ab + A_STG;
        const uint32_t bl = ab + 2 * A_STG;
        #pragma unroll
        for (int p = 0; p < 4; p++) {                 // A: 128 rows of k64
            int row = cprow + p * 32;
            uint32_t so = row * 128 + ((cpch ^ (row & 7)) << 4);
            cp16(ab + so, &Ain[(m0 + row) * 1024 + kk0 + cpch * 8]);
        }
        #pragma unroll
        for (int p = 0; p < 4; p++) {                 // B_hi: 128 rows
            int row = cprow + p * 32;
            uint32_t so = row * 128 + ((cpch ^ (row & 7)) << 4);
            cp16(bh + so, &g_B[(uint64_t)(n0p + row) * 2048 + kk0 + cpch * 8]);
        }
        #pragma unroll
        for (int p = 0; p < 4; p++) {                 // B_lo: 128 rows
            int row = cprow + p * 32;
            uint32_t so = row * 128 + ((cpch ^ (row & 7)) << 4);
            cp16(bl + so, &g_B[(uint64_t)(n0p + row) * 2048 + 1024 + kk0 + cpch * 8]);
        }
        cp_commit();
    };

    // fragment lane mapping
    const int a_r  = lane & 15;
    const int a_cb = lane >> 4;
    const int b_rr = (lane & 7) + ((lane >> 4) << 3);
    const int b_cb = (lane >> 3) & 1;

    issue(0);

    #pragma unroll 1
    for (int s = 0; s < NSTG; s++) {
        cp_wait<0>();                      // stage s landed (one group in flight)
        __syncthreads();                   // all warps done with buf s^1 & see stage s
        if (s + 1 < NSTG) issue(s + 1);    // prefetch next into the freed slot

        const uint32_t ab = sb + (s & (NBUF - 1)) * STG_BYTES;
        const uint32_t bh = ab + A_STG;
        const uint32_t bl = ab + 2 * A_STG;

        #pragma unroll
        for (int kk = 0; kk < 4; kk++) {
            const int kq = (kk + krot) & 3;   // per-warp phase rotation
            uint32_t af[4][4], bf[2][4];
            {
                int ch = kq * 2 + a_cb;
                #pragma unroll
                for (int mi = 0; mi < 4; mi++) {
                    int row = wm * 64 + mi * 16 + a_r;
                    ldsm4(af[mi], ab + row * 128 + ((ch ^ (row & 7)) << 4));
                }
            }
            // B_hi burst (warp's 32 cols = 2 ldsm4)
            {
                int ch = kq * 2 + b_cb;
                #pragma unroll
                for (int jp = 0; jp < 2; jp++) {
                    int row = wn * 32 + jp * 16 + b_rr;
                    ldsm4(bf[jp], bh + row * 128 + ((ch ^ (row & 7)) << 4));
                }
            }
            #pragma unroll
            for (int mi = 0; mi < 4; mi++)
                #pragma unroll
                for (int j = 0; j < 4; j++)
                    mma16816(acc[mi][j], af[mi], &bf[j >> 1][(j & 1) * 2]);
            // B_lo burst (reuse A frags and bf registers)
            {
                int ch = kq * 2 + b_cb;
                #pragma unroll
                for (int jp = 0; jp < 2; jp++) {
                    int row = wn * 32 + jp * 16 + b_rr;
                    ldsm4(bf[jp], bl + row * 128 + ((ch ^ (row & 7)) << 4));
                }
            }
            #pragma unroll
            for (int mi = 0; mi < 4; mi++)
                #pragma unroll
                for (int j = 0; j < 4; j++)
                    mma16816(acc[mi][j], af[mi], &bf[j >> 1][(j & 1) * 2]);
        }
    }

    // ---------------- epilogue ----------------
    // Thread owns cols C = n0p + wn*32 + j*8 + 2q + e, j=0..3, e=0..1.
    // With the new permutation: e = g&1, j&1 = g>>1, jj = j>>1 selects unit,
    //   u = ((n0p>>5) + wn)*8 + jj*4 + q.
    const int q  = lane & 3;
    const int tr = lane >> 2;
    float kwv[4][2], bsv[4][2];
    #pragma unroll
    for (int j = 0; j < 4; j++) {
        int C = n0p + wn * 32 + 8 * j + 2 * q;
        float2 kw2 = *reinterpret_cast<const float2*>(&g_kwP[C]);
        float2 bs2 = *reinterpret_cast<const float2*>(&g_biasP[C]);
        kwv[j][0] = kw2.x; kwv[j][1] = kw2.y;
        bsv[j][0] = bs2.x; bsv[j][1] = bs2.y;
    }
    const int ubase = ((n0p >> 5) + wn) * 8 + q;   // + jj*4

    #pragma unroll
    for (int mi = 0; mi < 4; mi++) {
        #pragma unroll
        for (int h = 0; h < 2; h++) {
            int row = m0 + wm * 64 + mi * 16 + tr + 8 * h;
            float xb = xsrc ? xsrc[row * xstride] : g_pred[row];
            #pragma unroll
            for (int jj = 0; jj < 2; jj++) {
                int u = ubase + jj * 4;
                float co = g_c[row * 1024 + u];
                float zi = acc[mi][2*jj    ][2*h    ] + xb * kwv[2*jj    ][0] + bsv[2*jj    ][0];
                float zf = acc[mi][2*jj    ][2*h + 1] + xb * kwv[2*jj    ][1] + bsv[2*jj    ][1];
                float zg = acc[mi][2*jj + 1][2*h    ] + xb * kwv[2*jj + 1][0] + bsv[2*jj + 1][0];
                float zo = acc[mi][2*jj + 1][2*h + 1] + xb * kwv[2*jj + 1][1] + bsv[2*jj + 1][1];
                float ig = sigm(zi);
                float fg = sigm(zf);
                float gg = tanh_fast(zg);
                float og = sigm(zo);
                float cc = fg * co + ig * gg;
                g_c[row * 1024 + u] = cc;
                float hh = og * tanh_fast(cc);
                Aout[row * 1024 + u] = __float2half_rn(hh);
            }
        }
    }
}

// ---------------- prediction head ----------------
__global__ void __launch_bounds__(256) pred_kernel(
    const float* __restrict__ w1, const float* __restrict__ b1,
    const float* __restrict__ w2, const float* __restrict__ b2,
    float* __restrict__ out, int tcol, int pin, int final_dense)
{
    int warp = (blockIdx.x * blockDim.x + threadIdx.x) >> 5;
    int lane = threadIdx.x & 31;
    if (warp >= BATCH) return;
    const __half* __restrict__ ha = &g_A[pin][warp * 1024];
    float s = 0.0f;
    #pragma unroll 4
    for (int k = lane; k < UNITS; k += 32)
        s = fmaf(__half2float(ha[k]), w1[k], s);
    #pragma unroll
    for (int off = 16; off; off >>= 1) s += __shfl_down_sync(0xffffffffu, s, off);
    if (lane == 0) {
        float x = fmaxf(s + b1[0], 0.0f);
        float p = final_dense ? fmaf(x, w2[0], b2[0]) : x;
        out[warp * OUT_STEPS + tcol] = p;
        g_pred[warp] = p;
    }
}

extern "C" void kernel_launch(void* const* d_in, const int* in_sizes, int n_in,
                              void* d_out, int out_size)
{
    const float* inputs = (const float*)d_in[0];
    const float* Kw     = (const float*)d_in[1];
    const float* R      = (const float*)d_in[2];
    const float* bias   = (const float*)d_in[3];
    const float* w1     = (const float*)d_in[4];
    const float* b1     = (const float*)d_in[5];
    const float* w2     = (const float*)d_in[6];
    const float* b2     = (const float*)d_in[7];
    float* out = (float*)d_out;

    cudaFuncSetAttribute(lstm_mma, cudaFuncAttributeMaxDynamicSharedMemorySize, SMEM_TOTAL);

    zero_kernel<<<(BATCH * UNITS + 255) / 256, 256>>>();
    prep_kernel<<<(4096 * 1024 + 255) / 256, 256>>>(R, Kw, bias);

    dim3 grid(BATCH / BM, 4096 / BN);   // (32, 32)
    int pp = 0;

    for (int t = 0; t < SEQ_LEN; t++) {
        lstm_mma<<<grid, NTHREADS, SMEM_TOTAL>>>(inputs + t, SEQ_LEN, pp);
        pp ^= 1;
    }
    pred_kernel<<<BATCH / 8, 256>>>(w1, b1, w2, b2, out, 0, pp, 0);

    for (int j = 1; j < OUT_STEPS; j++) {
        lstm_mma<<<grid, NTHREADS, SMEM_TOTAL>>>(nullptr, 1, pp);
        pp ^= 1;
        pred_kernel<<<BATCH / 8, 256>>>(w1, b1, w2, b2, out, j, pp, 1);
    }
}

// round 12
// speedup vs baseline: 1.6855x; 1.6855x over previous
#include <cuda_runtime.h>
#include <cuda_fp16.h>
#include <math.h>
#include <cstdint>

#define BATCH 4096
#define UNITS 1024
#define OUT_STEPS 200
#define SEQ_LEN 5

#define BK 64
#define NSTG 16          // K=1024, plain fp16 R
#define BM 128
#define BN 128           // permuted z columns (= 32 units x 4 gates)
#define NTHREADS 256

#define A_STG 16384                     // 128 rows x 128B (k64 fp16)
#define STG_BYTES (2 * 16384)           // A + B = 32KB
#define NBUF 3
#define SMEM_TOTAL (NBUF * STG_BYTES)   // 96KB -> 2 CTAs/SM

// ---------------- device globals ----------------
__device__ __half g_A[2][BATCH * 1024];   // ping-pong hidden state, fp16
__device__ __half g_B[4096 * 1024];       // permuted R (fp16), row C, K-major
__device__ float g_c[BATCH * UNITS];
__device__ float g_pred[BATCH];
__device__ float g_kwP[4096];
__device__ float g_biasP[4096];

// ---------------- helpers ----------------
__device__ __forceinline__ uint32_t smem_u32(const void* p) {
    uint32_t a;
    asm("{ .reg .u64 t; cvta.to.shared.u64 t, %1; cvt.u32.u64 %0, t; }" : "=r"(a) : "l"(p));
    return a;
}
__device__ __forceinline__ void cp16(uint32_t saddr, const void* gaddr) {
    asm volatile("cp.async.cg.shared.global [%0], [%1], 16;" :: "r"(saddr), "l"(gaddr));
}
__device__ __forceinline__ void cp_commit() {
    asm volatile("cp.async.commit_group;" ::: "memory");
}
template<int N> __device__ __forceinline__ void cp_wait() {
    asm volatile("cp.async.wait_group %0;" :: "n"(N) : "memory");
}
__device__ __forceinline__ void ldsm4(uint32_t* r, uint32_t addr) {
    asm volatile("ldmatrix.sync.aligned.m8n8.x4.shared.b16 {%0,%1,%2,%3}, [%4];"
                 : "=r"(r[0]), "=r"(r[1]), "=r"(r[2]), "=r"(r[3]) : "r"(addr));
}
__device__ __forceinline__ void mma16816(float* c, const uint32_t* a, const uint32_t* b) {
    asm volatile(
        "mma.sync.aligned.m16n8k16.row.col.f32.f16.f16.f32 "
        "{%0,%1,%2,%3}, {%4,%5,%6,%7}, {%8,%9}, {%0,%1,%2,%3};"
        : "+f"(c[0]), "+f"(c[1]), "+f"(c[2]), "+f"(c[3])
        : "r"(a[0]), "r"(a[1]), "r"(a[2]), "r"(a[3]), "r"(b[0]), "r"(b[1]));
}
__device__ __forceinline__ float sigm(float x) { return 1.0f / (1.0f + __expf(-x)); }
__device__ __forceinline__ float tanh_fast(float x) {
    float t = __expf(-2.0f * fabsf(x));
    float r = (1.0f - t) / (1.0f + t);
    return copysignf(r, x);
}

// ---------------- prep: build permuted fp16 B ----------------
// Permuted column C <- (unit u, gate g):
//   C = (u>>4)*64 + (g>>1)*32 + (u&3)*8 + ((u>>2)&3)*2 + (g&1)
// Inverse: u = (C>>6)*16 + ((C>>1)&3)*4 + ((C>>3)&3) ; g = ((C>>5)&1)*2 + (C&1)
__global__ void prep_kernel(const float* __restrict__ R, const float* __restrict__ Kw,
                            const float* __restrict__ bias) {
    int idx = blockIdx.x * blockDim.x + threadIdx.x;   // np*1024 + k
    if (idx >= 4096 * 1024) return;
    int np = idx >> 10;
    int k  = idx & 1023;
    int u = ((np >> 6) << 4) | (((np >> 1) & 3) << 2) | ((np >> 3) & 3);
    int g = (((np >> 5) & 1) << 1) | (np & 1);
    int n = g * 1024 + u;
    float v = R[k * 4096 + n];
    g_B[np * 1024 + k] = __float2half_rn(v);
    if (k == 0) { g_kwP[np] = Kw[n]; g_biasP[np] = bias[n]; }
}

__global__ void zero_kernel() {
    int i = blockIdx.x * blockDim.x + threadIdx.x;
    if (i < BATCH * UNITS) {
        g_c[i] = 0.0f;
        if (i < BATCH * 512) ((uint32_t*)g_A[0])[i] = 0;   // 2M halfs
    }
}

// ---------------- fused LSTM step (fp16 mma.sync GEMM + gates) ----------------
__global__ void __launch_bounds__(NTHREADS, 2) lstm_mma(const float* __restrict__ xsrc,
                                                        int xstride, int pin) {
    extern __shared__ char smem[];
    const uint32_t sb = smem_u32(smem);
    const int tid  = threadIdx.x;
    const int wid  = tid >> 5;
    const int lane = tid & 31;
    const int wm   = wid >> 1;       // 0..3 (32-row group)
    const int wn   = wid & 1;        // 0..1 (64-col group)
    const int krot = wid & 3;        // kk-phase rotation per warp
    const int m0   = blockIdx.x * BM;
    const int n0p  = blockIdx.y * BN;   // permuted-col base

    const __half* __restrict__ Ain = g_A[pin];
    __half* __restrict__ Aout = g_A[pin ^ 1];

    float acc[2][8][4];
    #pragma unroll
    for (int a = 0; a < 2; a++)
        #pragma unroll
        for (int b = 0; b < 8; b++)
            #pragma unroll
            for (int c = 0; c < 4; c++) acc[a][b][c] = 0.0f;

    const int cprow = tid >> 3;     // 0..31
    const int cpch  = tid & 7;

    auto issue = [&](int s) {
        const int buf = s % NBUF;
        const int kk0 = s * BK;
        const uint32_t ab = sb + buf * STG_BYTES;
        const uint32_t bb = ab + A_STG;
        #pragma unroll
        for (int p = 0; p < 4; p++) {                 // A: 128 rows of k64
            int row = cprow + p * 32;
            uint32_t so = row * 128 + ((cpch ^ (row & 7)) << 4);
            cp16(ab + so, &Ain[(m0 + row) * 1024 + kk0 + cpch * 8]);
        }
        #pragma unroll
        for (int p = 0; p < 4; p++) {                 // B: 128 rows
            int row = cprow + p * 32;
            uint32_t so = row * 128 + ((cpch ^ (row & 7)) << 4);
            cp16(bb + so, &g_B[(uint64_t)(n0p + row) * 1024 + kk0 + cpch * 8]);
        }
        cp_commit();
    };

    // fragment lane mapping
    const int a_r  = lane & 15;
    const int a_cb = lane >> 4;
    const int b_rr = (lane & 7) + ((lane >> 4) << 3);
    const int b_cb = (lane >> 3) & 1;

    issue(0);
    issue(1);

    #pragma unroll 1
    for (int s = 0; s < NSTG; s++) {
        if (s == NSTG - 1) cp_wait<0>();
        else               cp_wait<1>();   // stage s landed
        __syncthreads();                   // data visible + slot (s-1)%NBUF free
        if (s + 2 < NSTG) issue(s + 2);    // prefetch 2 ahead into freed slot

        const uint32_t ab = sb + (s % NBUF) * STG_BYTES;
        const uint32_t bb = ab + A_STG;

        #pragma unroll
        for (int kk = 0; kk < 4; kk++) {
            const int kq = (kk + krot) & 3;   // per-warp phase rotation
            uint32_t af[2][4], bf[4][4];
            {
                int ch = kq * 2 + a_cb;
                #pragma unroll
                for (int mi = 0; mi < 2; mi++) {
                    int row = wm * 32 + mi * 16 + a_r;
                    ldsm4(af[mi], ab + row * 128 + ((ch ^ (row & 7)) << 4));
                }
            }
            {
                int ch = kq * 2 + b_cb;
                #pragma unroll
                for (int jp = 0; jp < 4; jp++) {
                    int row = wn * 64 + jp * 16 + b_rr;
                    ldsm4(bf[jp], bb + row * 128 + ((ch ^ (row & 7)) << 4));
                }
            }
            #pragma unroll
            for (int mi = 0; mi < 2; mi++)
                #pragma unroll
                for (int j = 0; j < 8; j++)
                    mma16816(acc[mi][j], af[mi], &bf[j >> 1][(j & 1) * 2]);
        }
    }

    // ---------------- epilogue ----------------
    const int q  = lane & 3;
    const int tr = lane >> 2;
    float kwv[8][2], bsv[8][2];
    #pragma unroll
    for (int j = 0; j < 8; j++) {
        int C = n0p + wn * 64 + 8 * j + 2 * q;
        float2 kw2 = *reinterpret_cast<const float2*>(&g_kwP[C]);
        float2 bs2 = *reinterpret_cast<const float2*>(&g_biasP[C]);
        kwv[j][0] = kw2.x; kwv[j][1] = kw2.y;
        bsv[j][0] = bs2.x; bsv[j][1] = bs2.y;
    }
    // global 64-col-group index = blockIdx.y*2 + wn; 16 units per group
    const int u0 = (blockIdx.y * 2 + wn) * 16 + 4 * q;   // 4 consecutive units

    #pragma unroll
    for (int mi = 0; mi < 2; mi++) {
        #pragma unroll
        for (int h = 0; h < 2; h++) {
            int row = m0 + wm * 32 + mi * 16 + tr + 8 * h;
            float xb = xsrc ? xsrc[row * xstride] : g_pred[row];
            float4 cold = *reinterpret_cast<const float4*>(&g_c[row * 1024 + u0]);
            float co[4] = {cold.x, cold.y, cold.z, cold.w};
            float cn[4];
            __half hh4[4];
            #pragma unroll
            for (int jl = 0; jl < 4; jl++) {
                float zi = acc[mi][jl    ][2 * h    ] + xb * kwv[jl    ][0] + bsv[jl    ][0];
                float zf = acc[mi][jl    ][2 * h + 1] + xb * kwv[jl    ][1] + bsv[jl    ][1];
                float zg = acc[mi][jl + 4][2 * h    ] + xb * kwv[jl + 4][0] + bsv[jl + 4][0];
                float zo = acc[mi][jl + 4][2 * h + 1] + xb * kwv[jl + 4][1] + bsv[jl + 4][1];
                float ig = sigm(zi);
                float fg = sigm(zf);
                float gg = tanh_fast(zg);
                float og = sigm(zo);
                float cc = fg * co[jl] + ig * gg;
                cn[jl] = cc;
                float hh = og * tanh_fast(cc);
                hh4[jl] = __float2half_rn(hh);
            }
            float4 cv = {cn[0], cn[1], cn[2], cn[3]};
            *reinterpret_cast<float4*>(&g_c[row * 1024 + u0]) = cv;
            uint2 hv;
            memcpy(&hv, hh4, 8);
            *reinterpret_cast<uint2*>(&Aout[row * 1024 + u0]) = hv;
        }
    }
}

// ---------------- prediction head ----------------
__global__ void __launch_bounds__(256) pred_kernel(
    const float* __restrict__ w1, const float* __restrict__ b1,
    const float* __restrict__ w2, const float* __restrict__ b2,
    float* __restrict__ out, int tcol, int pin, int final_dense)
{
    int warp = (blockIdx.x * blockDim.x + threadIdx.x) >> 5;
    int lane = threadIdx.x & 31;
    if (warp >= BATCH) return;
    const __half* __restrict__ ha = &g_A[pin][warp * 1024];
    float s = 0.0f;
    #pragma unroll 4
    for (int k = lane; k < UNITS; k += 32)
        s = fmaf(__half2float(ha[k]), w1[k], s);
    #pragma unroll
    for (int off = 16; off; off >>= 1) s += __shfl_down_sync(0xffffffffu, s, off);
    if (lane == 0) {
        float x = fmaxf(s + b1[0], 0.0f);
        float p = final_dense ? fmaf(x, w2[0], b2[0]) : x;
        out[warp * OUT_STEPS + tcol] = p;
        g_pred[warp] = p;
    }
}

extern "C" void kernel_launch(void* const* d_in, const int* in_sizes, int n_in,
                              void* d_out, int out_size)
{
    const float* inputs = (const float*)d_in[0];
    const float* Kw     = (const float*)d_in[1];
    const float* R      = (const float*)d_in[2];
    const float* bias   = (const float*)d_in[3];
    const float* w1     = (const float*)d_in[4];
    const float* b1     = (const float*)d_in[5];
    const float* w2     = (const float*)d_in[6];
    const float* b2     = (const float*)d_in[7];
    float* out = (float*)d_out;

    cudaFuncSetAttribute(lstm_mma, cudaFuncAttributeMaxDynamicSharedMemorySize, SMEM_TOTAL);

    zero_kernel<<<(BATCH * UNITS + 255) / 256, 256>>>();
    prep_kernel<<<(4096 * 1024 + 255) / 256, 256>>>(R, Kw, bias);

    dim3 grid(BATCH / BM, 4096 / BN);   // (32, 32)
    int pp = 0;

    for (int t = 0; t < SEQ_LEN; t++) {
        lstm_mma<<<grid, NTHREADS, SMEM_TOTAL>>>(inputs + t, SEQ_LEN, pp);
        pp ^= 1;
    }
    pred_kernel<<<BATCH / 8, 256>>>(w1, b1, w2, b2, out, 0, pp, 0);

    for (int j = 1; j < OUT_STEPS; j++) {
        lstm_mma<<<grid, NTHREADS, SMEM_TOTAL>>>(nullptr, 1, pp);
        pp ^= 1;
        pred_kernel<<<BATCH / 8, 256>>>(w1, b1, w2, b2, out, j, pp, 1);
    }
}